// round 7
// baseline (speedup 1.0000x reference)
#include <cuda_runtime.h>
#include <cuda_fp16.h>
#include <cstdint>

// Problem constants
#define T_TOK 2048
#define HDIM  1024
#define FDIM  1024
#define NEXP  8
#define TOPK  2
#define NPAIR (T_TOK * TOPK)

// Tiling
#define BM 128
#define BK 64
#define NCH (HDIM / BK)          // 16 chunks (HDIM == FDIM)
#define MAX_TILES 40
#define PAD_ROWS (MAX_TILES * BM)

// fp16 smem rows of 64 halfs (128B), stride 144 B (9 x 16B granules,
// gcd(9,8)=1 -> ldmatrix conflict-free across 8 rows).
#define ROWB 144
#define TILEB (BM * ROWB)        // 18432 B (A and B tiles both 128 rows)
#define A_STAGES 3
#define B_STAGES 2
#define SMEM_BYTES (A_STAGES * TILEB + B_STAGES * TILEB)   // 92160

// Scratch (no allocations allowed)
__device__ int    d_sorted[PAD_ROWS];
__device__ int    d_tile_expert[MAX_TILES];
__device__ int    d_ntiles;
__device__ __half d_hs16[(size_t)T_TOK * HDIM];     // 4 MB
__device__ __half d_act[(size_t)PAD_ROWS * FDIM];   // 10 MB
__device__ float  d_y2[(size_t)NPAIR * HDIM];       // 16 MB

// ---------------------------------------------------------------------------
// Helpers
// ---------------------------------------------------------------------------
__device__ __forceinline__ uint32_t smem_u32(const void* p) {
    uint32_t a;
    asm("{ .reg .u64 t; cvta.to.shared.u64 t, %1; cvt.u32.u64 %0, t; }" : "=r"(a) : "l"(p));
    return a;
}
__device__ __forceinline__ uint32_t f2h2(float lo, float hi) {
    __half2 h = __floats2half2_rn(lo, hi);
    return *(uint32_t*)&h;
}
__device__ __forceinline__ void cpa16(uint32_t dst, const void* src) {
    asm volatile("cp.async.cg.shared.global [%0], [%1], 16;" :: "r"(dst), "l"(src));
}
#define CPA_COMMIT() asm volatile("cp.async.commit_group;" ::: "memory")
#define CPA_WAIT1()  asm volatile("cp.async.wait_group 1;" ::: "memory")

__device__ __forceinline__ void ldsm4(uint32_t* r, uint32_t addr) {
    asm volatile("ldmatrix.sync.aligned.m8n8.x4.shared.b16 {%0,%1,%2,%3}, [%4];"
                 : "=r"(r[0]), "=r"(r[1]), "=r"(r[2]), "=r"(r[3]) : "r"(addr));
}
__device__ __forceinline__ void mma16(float* d, const uint32_t* a, const uint32_t* b) {
    asm volatile(
        "mma.sync.aligned.m16n8k16.row.col.f32.f16.f16.f32 "
        "{%0,%1,%2,%3}, {%4,%5,%6,%7}, {%8,%9}, {%0,%1,%2,%3};"
        : "+f"(d[0]), "+f"(d[1]), "+f"(d[2]), "+f"(d[3])
        : "r"(a[0]), "r"(a[1]), "r"(a[2]), "r"(a[3]), "r"(b[0]), "r"(b[1]));
}

// ---------------------------------------------------------------------------
// Setup: block 0 = routing; blocks 1.. = hs fp32 -> fp16 convert
// ---------------------------------------------------------------------------
__global__ void setup_kernel(const float* __restrict__ hs, const int* __restrict__ ids) {
    int tid = threadIdx.x;
    if (blockIdx.x == 0) {
        __shared__ int s_cnt[NEXP], s_start[NEXP], s_cur[NEXP];
        if (tid < NEXP) s_cnt[tid] = 0;
        __syncthreads();
        for (int p = tid; p < NPAIR; p += blockDim.x) atomicAdd(&s_cnt[ids[p]], 1);
        __syncthreads();
        if (tid == 0) {
            int acc = 0, nt = 0;
            for (int e = 0; e < NEXP; e++) {
                s_start[e] = acc;
                int te = (s_cnt[e] + BM - 1) / BM;
                for (int i = 0; i < te; i++) d_tile_expert[nt + i] = e;
                nt += te;
                acc += te * BM;
            }
            d_ntiles = nt;
        }
        __syncthreads();
        for (int i = tid; i < PAD_ROWS; i += blockDim.x) d_sorted[i] = -1;
        if (tid < NEXP) s_cur[tid] = s_start[tid];
        __syncthreads();
        for (int p = tid; p < NPAIR; p += blockDim.x) {
            int pos = atomicAdd(&s_cur[ids[p]], 1);
            d_sorted[pos] = p;
        }
    } else {
        int i = (blockIdx.x - 1) * 256 + tid;      // over T*H/8
        const float4* s = (const float4*)hs;
        float4 a = s[i * 2], b = s[i * 2 + 1];
        uint4 o;
        o.x = f2h2(a.x, a.y); o.y = f2h2(a.z, a.w);
        o.z = f2h2(b.x, b.y); o.w = f2h2(b.z, b.w);
        ((uint4*)d_hs16)[i] = o;
    }
}

// ---------------------------------------------------------------------------
// GEMM1: act = silu(x @ Wg^T) * (x @ Wu^T).
// 128 thr (4 warps, 2x2), warp tile 64m x 32f DUAL (gate+up). Grid (40,16).
// A (fp16): 3-stage cp.async BK=64. B (fp32 -> fp16): 2-stage, half-split regs.
// ---------------------------------------------------------------------------
__global__ __launch_bounds__(128, 2)
void gemm1_kernel(const float* __restrict__ gw) {
    int tile = blockIdx.x;
    if (tile >= d_ntiles) return;
    int e  = d_tile_expert[tile];
    int f0 = blockIdx.y * 64;

    extern __shared__ __align__(16) char smem[];
    __shared__ int s_tok[BM];

    int tid = threadIdx.x, lane = tid & 31, warp = tid >> 5;
    if (tid < BM) {
        int sp = d_sorted[tile * BM + tid];
        s_tok[tid] = (sp >= 0) ? (sp >> 1) : 0;
    }
    __syncthreads();

    const float* gwe = gw + (size_t)e * (2 * FDIM) * HDIM;
    uint32_t sb = smem_u32(smem);
    uint32_t bbase0 = sb + A_STAGES * TILEB;

    // A cp.async: 128 rows x 64 halfs = 1024 x 16B slots, 8/thread
    int ar[8], ac8[8];
    const __half* asrc[8];
    #pragma unroll
    for (int i = 0; i < 8; i++) {
        int idx = tid + i * 128;
        ar[i] = idx >> 3; ac8[i] = idx & 7;
        asrc[i] = d_hs16 + (size_t)s_tok[ar[i]] * HDIM + ac8[i] * 8;
    }
    auto issueA = [&](int c) {
        uint32_t ab = sb + (c % A_STAGES) * TILEB;
        #pragma unroll
        for (int i = 0; i < 8; i++)
            cpa16(ab + ar[i] * ROWB + ac8[i] * 16, asrc[i] + c * BK);
    };

    // B: 128 rows (64 gate + 64 up) x 64 fp32 = 2048 float4; half h covers
    // rows [h*64, h*64+64): 8 float4/thread per half.
    int br[2][8], bc4[2][8];
    const float* bsrc[2][8];
    #pragma unroll
    for (int h = 0; h < 2; h++)
        #pragma unroll
        for (int i = 0; i < 8; i++) {
            int idx = tid + (h * 8 + i) * 128;
            br[h][i] = idx >> 4; bc4[h][i] = idx & 15;
            int grow = (br[h][i] < 64) ? (f0 + br[h][i]) : (FDIM + f0 + (br[h][i] - 64));
            bsrc[h][i] = gwe + (size_t)grow * HDIM + bc4[h][i] * 4;
        }
    float4 bbuf[8];
    auto loadB = [&](int c, int h) {
        #pragma unroll
        for (int i = 0; i < 8; i++) bbuf[i] = *(const float4*)(bsrc[h][i] + c * BK);
    };
    auto stsB = [&](int c, int h) {
        char* bs = smem + A_STAGES * TILEB + (c & 1) * TILEB;
        #pragma unroll
        for (int i = 0; i < 8; i++)
            *(uint2*)(bs + br[h][i] * ROWB + bc4[h][i] * 8) =
                make_uint2(f2h2(bbuf[i].x, bbuf[i].y), f2h2(bbuf[i].z, bbuf[i].w));
    };

    int wm = warp & 1, wn = warp >> 1;
    int m_base = wm * 64, f_base = wn * 32;

    int g = lane >> 3;
    int a_row = (g & 1) * 8 + (lane & 7);
    int a_kb  = (g >> 1) * 16;
    int b_row = (g >> 1) * 8 + (lane & 7);
    int b_kb  = (g & 1) * 16;

    float accG[4][4][4], accU[4][4][4];
    #pragma unroll
    for (int mt = 0; mt < 4; mt++)
        #pragma unroll
        for (int nt = 0; nt < 4; nt++)
            #pragma unroll
            for (int i = 0; i < 4; i++) { accG[mt][nt][i] = 0.f; accU[mt][nt][i] = 0.f; }

    issueA(0); CPA_COMMIT();
    issueA(1); CPA_COMMIT();
    loadB(0, 0); stsB(0, 0); loadB(0, 1); stsB(0, 1);

    for (int c = 0; c < NCH; c++) {
        CPA_WAIT1();
        __syncthreads();

        uint32_t Ab = sb + (c % A_STAGES) * TILEB;
        uint32_t Bb = bbase0 + (c & 1) * TILEB;
        bool more = (c + 1 < NCH);

        #pragma unroll
        for (int kf = 0; kf < 4; kf++) {
            uint32_t af[4][4], bg[8], bu[8];
            #pragma unroll
            for (int mt = 0; mt < 4; mt++)
                ldsm4(af[mt], Ab + (m_base + mt * 16 + a_row) * ROWB + kf * 32 + a_kb);
            #pragma unroll
            for (int p = 0; p < 2; p++) {
                ldsm4(bg + p * 4, Bb + (f_base + p * 16 + b_row) * ROWB + kf * 32 + b_kb);
                ldsm4(bu + p * 4, Bb + (64 + f_base + p * 16 + b_row) * ROWB + kf * 32 + b_kb);
            }
            if (kf == 0 && more) loadB(c + 1, 0);
            if (kf == 2 && more) loadB(c + 1, 1);
            #pragma unroll
            for (int mt = 0; mt < 4; mt++)
                #pragma unroll
                for (int nt = 0; nt < 4; nt++) {
                    mma16(accG[mt][nt], af[mt], bg + nt * 2);
                    mma16(accU[mt][nt], af[mt], bu + nt * 2);
                }
            if (kf == 1 && more) stsB(c + 1, 0);
            if (kf == 3 && more) stsB(c + 1, 1);
        }
        if (c + 2 < NCH) issueA(c + 2);
        CPA_COMMIT();
    }

    // Epilogue: silu(g)*u -> fp16 act scratch
    #pragma unroll
    for (int mt = 0; mt < 4; mt++)
        #pragma unroll
        for (int nt = 0; nt < 4; nt++)
            #pragma unroll
            for (int half = 0; half < 2; half++) {
                int r  = m_base + mt * 16 + (lane >> 2) + half * 8;
                int cc = f0 + f_base + nt * 8 + (lane & 3) * 2;
                float g0 = accG[mt][nt][half * 2 + 0];
                float g1 = accG[mt][nt][half * 2 + 1];
                float u0 = accU[mt][nt][half * 2 + 0];
                float u1 = accU[mt][nt][half * 2 + 1];
                float a0 = g0 / (1.f + __expf(-g0)) * u0;
                float a1 = g1 / (1.f + __expf(-g1)) * u1;
                *(__half2*)&d_act[(size_t)(tile * BM + r) * FDIM + cc] =
                    __floats2half2_rn(a0, a1);
            }
}

// ---------------------------------------------------------------------------
// GEMM2: y2[pair] = tw[pair] * (act @ Wd[e]^T).
// 128 thr (4 warps, 2x2), warp tile 64x64, BN=128. Grid (40,8).
// ---------------------------------------------------------------------------
__global__ __launch_bounds__(128, 2)
void gemm2_kernel(const float* __restrict__ dw, const float* __restrict__ tw) {
    int tile = blockIdx.x;
    if (tile >= d_ntiles) return;
    int e  = d_tile_expert[tile];
    int h0 = blockIdx.y * 128;

    extern __shared__ __align__(16) char smem[];

    int tid = threadIdx.x, lane = tid & 31, warp = tid >> 5;
    const float*  dwe  = dw + (size_t)e * HDIM * FDIM;
    const __half* arow = d_act + (size_t)tile * BM * FDIM;
    uint32_t sb = smem_u32(smem);
    uint32_t bbase0 = sb + A_STAGES * TILEB;

    // A cp.async: 1024 x 16B slots, 8/thread
    int ar[8], ac8[8];
    #pragma unroll
    for (int i = 0; i < 8; i++) {
        int idx = tid + i * 128;
        ar[i] = idx >> 3; ac8[i] = idx & 7;
    }
    auto issueA = [&](int c) {
        uint32_t ab = sb + (c % A_STAGES) * TILEB;
        #pragma unroll
        for (int i = 0; i < 8; i++)
            cpa16(ab + ar[i] * ROWB + ac8[i] * 16,
                  arow + (size_t)ar[i] * FDIM + c * BK + ac8[i] * 8);
    };

    // B: 128 rows x 64 fp32, halves of 8 float4/thread
    int br[2][8], bc4[2][8];
    #pragma unroll
    for (int h = 0; h < 2; h++)
        #pragma unroll
        for (int i = 0; i < 8; i++) {
            int idx = tid + (h * 8 + i) * 128;
            br[h][i] = idx >> 4; bc4[h][i] = idx & 15;
        }
    float4 bbuf[8];
    auto loadB = [&](int c, int h) {
        #pragma unroll
        for (int i = 0; i < 8; i++)
            bbuf[i] = *(const float4*)(dwe + (size_t)(h0 + br[h][i]) * FDIM + c * BK + bc4[h][i] * 4);
    };
    auto stsB = [&](int c, int h) {
        char* bs = smem + A_STAGES * TILEB + (c & 1) * TILEB;
        #pragma unroll
        for (int i = 0; i < 8; i++)
            *(uint2*)(bs + br[h][i] * ROWB + bc4[h][i] * 8) =
                make_uint2(f2h2(bbuf[i].x, bbuf[i].y), f2h2(bbuf[i].z, bbuf[i].w));
    };

    int wm = warp & 1, wn = warp >> 1;
    int m_base = wm * 64, n_base = wn * 64;

    int g = lane >> 3;
    int a_row = (g & 1) * 8 + (lane & 7);
    int a_kb  = (g >> 1) * 16;
    int b_row = (g >> 1) * 8 + (lane & 7);
    int b_kb  = (g & 1) * 16;

    float acc[4][8][4];
    #pragma unroll
    for (int mt = 0; mt < 4; mt++)
        #pragma unroll
        for (int nt = 0; nt < 8; nt++)
            #pragma unroll
            for (int i = 0; i < 4; i++) acc[mt][nt][i] = 0.f;

    issueA(0); CPA_COMMIT();
    issueA(1); CPA_COMMIT();
    loadB(0, 0); stsB(0, 0); loadB(0, 1); stsB(0, 1);

    for (int c = 0; c < NCH; c++) {
        CPA_WAIT1();
        __syncthreads();

        uint32_t Ab = sb + (c % A_STAGES) * TILEB;
        uint32_t Bb = bbase0 + (c & 1) * TILEB;
        bool more = (c + 1 < NCH);

        #pragma unroll
        for (int kf = 0; kf < 4; kf++) {
            uint32_t af[4][4], bf[16];
            #pragma unroll
            for (int mt = 0; mt < 4; mt++)
                ldsm4(af[mt], Ab + (m_base + mt * 16 + a_row) * ROWB + kf * 32 + a_kb);
            #pragma unroll
            for (int p = 0; p < 4; p++)
                ldsm4(bf + p * 4, Bb + (n_base + p * 16 + b_row) * ROWB + kf * 32 + b_kb);
            if (kf == 0 && more) loadB(c + 1, 0);
            if (kf == 2 && more) loadB(c + 1, 1);
            #pragma unroll
            for (int mt = 0; mt < 4; mt++)
                #pragma unroll
                for (int nt = 0; nt < 8; nt++)
                    mma16(acc[mt][nt], af[mt], bf + nt * 2);
            if (kf == 1 && more) stsB(c + 1, 0);
            if (kf == 3 && more) stsB(c + 1, 1);
        }
        if (c + 2 < NCH) issueA(c + 2);
        CPA_COMMIT();
    }

    // Epilogue: scale by topk weight into per-pair y2 (fp32)
    #pragma unroll
    for (int mt = 0; mt < 4; mt++)
        #pragma unroll
        for (int half = 0; half < 2; half++) {
            int r  = m_base + mt * 16 + (lane >> 2) + half * 8;
            int sp = d_sorted[tile * BM + r];
            if (sp < 0) continue;
            float w = tw[sp];
            #pragma unroll
            for (int nt = 0; nt < 8; nt++) {
                int cc = h0 + n_base + nt * 8 + (lane & 3) * 2;
                float v0 = w * acc[mt][nt][half * 2 + 0];
                float v1 = w * acc[mt][nt][half * 2 + 1];
                *(float2*)&d_y2[(size_t)sp * HDIM + cc] = make_float2(v0, v1);
            }
        }
}

// ---------------------------------------------------------------------------
// Reduce: out[t] = y2[2t] + y2[2t+1]
// ---------------------------------------------------------------------------
__global__ void reduce_kernel(float* __restrict__ out) {
    int i = blockIdx.x * blockDim.x + threadIdx.x;
    int t = i >> 8, c4 = i & 255;
    const float4* y = (const float4*)d_y2;
    float4 a = y[(size_t)(t * 2) * 256 + c4];
    float4 b = y[(size_t)(t * 2 + 1) * 256 + c4];
    ((float4*)out)[i] = make_float4(a.x + b.x, a.y + b.y, a.z + b.z, a.w + b.w);
}

// ---------------------------------------------------------------------------
extern "C" void kernel_launch(void* const* d_in, const int* in_sizes, int n_in,
                              void* d_out, int out_size) {
    const float* hs  = (const float*)d_in[0];
    const float* tw  = (const float*)d_in[1];
    const int*   ids = (const int*)d_in[2];
    const float* gw  = (const float*)d_in[3];
    const float* dw  = (const float*)d_in[4];

    cudaFuncSetAttribute(gemm1_kernel, cudaFuncAttributeMaxDynamicSharedMemorySize, SMEM_BYTES);
    cudaFuncSetAttribute(gemm2_kernel, cudaFuncAttributeMaxDynamicSharedMemorySize, SMEM_BYTES);

    setup_kernel<<<1 + T_TOK * HDIM / 8 / 256, 256>>>(hs, ids);
    gemm1_kernel<<<dim3(MAX_TILES, FDIM / 64), 128, SMEM_BYTES>>>(gw);
    gemm2_kernel<<<dim3(MAX_TILES, HDIM / 128), 128, SMEM_BYTES>>>(dw, tw);
    reduce_kernel<<<(T_TOK * HDIM / 4) / 256, 256>>>((float*)d_out);
}